// round 5
// baseline (speedup 1.0000x reference)
#include <cuda_runtime.h>

#define B_ 4
#define N_ 2048
#define DIN 128
#define H_ 4
#define HD_ 32
#define BH (B_*H_)
#define NEG_SLOPE 0.2f
#define CH 128            // j-chunk staged in smem

// Scratch (device globals: no allocation allowed in kernel_launch)
__device__ float g_ht[BH*HD_*N_];    // projected features TRANSPOSED: [(b*H+h)*HD+d][n]
__device__ float g_Wt[DIN*DIN];      // W transposed: [k][o]
__device__ float g_ei[BH*N_];        // [(b*H+h)*N + n]
__device__ float g_ej[BH*N_];
__device__ float g_maxej[BH*N_];     // masked row-max of ej per (b,h,i)

// ---------------------------------------------------------------------------
// Kernel 0: transpose W so the GEMM reads it coalesced
// ---------------------------------------------------------------------------
__global__ void k_transpose(const float* __restrict__ W) {
    int k = blockIdx.x, o = threadIdx.x;
    g_Wt[k*DIN + o] = W[o*DIN + k];
}

// ---------------------------------------------------------------------------
// Kernel 1: h = x @ W^T  (+ fused ei/ej), writing h TRANSPOSED per (b,head,d)
// so k_attn can stage it with coalesced float4s along j.
// ---------------------------------------------------------------------------
__global__ void __launch_bounds__(128) k_gemm(const float* __restrict__ x,
                                              const float* __restrict__ a) {
    __shared__ float xs[32][DIN];
    int row0 = blockIdx.x * 32;
    int tid = threadIdx.x;

    const float4* xsrc = (const float4*)(x + (size_t)row0 * DIN);
    float4* xdst = (float4*)&xs[0][0];
    #pragma unroll
    for (int t = tid; t < 32*DIN/4; t += 128) xdst[t] = xsrc[t];
    __syncthreads();

    int o = tid;
    float acc[32];
    #pragma unroll
    for (int r = 0; r < 32; r++) acc[r] = 0.f;

    for (int k = 0; k < DIN; k++) {
        float w = g_Wt[k*DIN + o];
        #pragma unroll
        for (int r = 0; r < 32; r++) acc[r] += xs[r][k] * w;
    }

    int head = tid >> 5, d = tid & 31;
    int b = row0 / N_;                 // whole block is inside one batch (N_%32==0)
    int bh = b*H_ + head;

    // transposed store: g_ht[(bh*HD+d)][n], n = row0..row0+31, straight from regs
    size_t base = ((size_t)bh*HD_ + d)*N_ + (row0 % N_);
    #pragma unroll
    for (int r4 = 0; r4 < 8; r4++) {
        *(float4*)&g_ht[base + r4*4] =
            make_float4(acc[r4*4+0], acc[r4*4+1], acc[r4*4+2], acc[r4*4+3]);
    }

    float a1 = a[head*2*HD_ + d];
    float a2 = a[head*2*HD_ + HD_ + d];
    #pragma unroll
    for (int r = 0; r < 32; r++) {
        float p1 = acc[r] * a1;
        float p2 = acc[r] * a2;
        #pragma unroll
        for (int off = 16; off > 0; off >>= 1) {
            p1 += __shfl_xor_sync(0xffffffffu, p1, off);
            p2 += __shfl_xor_sync(0xffffffffu, p2, off);
        }
        if (d == 0) {
            int n = (row0 % N_) + r;
            g_ei[bh*N_ + n] = p1;
            g_ej[bh*N_ + n] = p2;
        }
    }
}

// ---------------------------------------------------------------------------
// Kernel 2: masked row-max of ej (leaky is monotone, so the softmax row max
// is leaky(ei_i + max_{adj!=0} ej_j) -- computed without touching h).
// ---------------------------------------------------------------------------
__global__ void __launch_bounds__(256) k_maxej(const int* __restrict__ adj) {
    int i = blockIdx.x;
    int tid = threadIdx.x;
    const float NEG_INF = __int_as_float(0xff800000);

    float m[BH];
    #pragma unroll
    for (int q = 0; q < BH; q++) m[q] = NEG_INF;

    for (int j = tid; j < N_; j += 256) {
        if (adj[(size_t)i*N_ + j] != 0) {
            #pragma unroll
            for (int q = 0; q < BH; q++) m[q] = fmaxf(m[q], g_ej[q*N_ + j]);
        }
    }

    __shared__ float red[8][BH];
    #pragma unroll
    for (int q = 0; q < BH; q++) {
        float v = m[q];
        #pragma unroll
        for (int off = 16; off > 0; off >>= 1)
            v = fmaxf(v, __shfl_xor_sync(0xffffffffu, v, off));
        m[q] = v;
    }
    if ((tid & 31) == 0) {
        #pragma unroll
        for (int q = 0; q < BH; q++) red[tid >> 5][q] = m[q];
    }
    __syncthreads();
    if (tid < BH) {
        float v = red[0][tid];
        #pragma unroll
        for (int w2 = 1; w2 < 8; w2++) v = fmaxf(v, red[w2][tid]);
        g_maxej[tid*N_ + i] = v;
    }
}

// ---------------------------------------------------------------------------
// Kernel 3: fused masked softmax + aggregation.
// grid = (16 (b,h), 64 i-tiles), 8 warps, warp owns 4 i-rows, lane = d.
//   - hs_t[d][j] transposed j-chunk (+4 pad -> conflict-free LDS.128 along j)
//   - ps2[w][j][ii] so one STS.128 writes p0..p3 and one broadcast LDS.128
//     yields two f32x2 pairs
//   - accumulation in packed fma.rn.f32x2 (halves FFMA instruction count)
// ---------------------------------------------------------------------------
__global__ void __launch_bounds__(256) k_attn(const int* __restrict__ adj,
                                              float* __restrict__ out) {
    __shared__ float hs_t[HD_][CH+4];      // ~16.9 KB, transposed h chunk
    __shared__ float ps2[8][32][4];        // 4 KB attn weights, [warp][j][ii]

    int bh = blockIdx.x;
    int b = bh >> 2, head = bh & 3;
    int tid = threadIdx.x, w = tid >> 5, lane = tid & 31;

    int i0 = blockIdx.y*32 + w*4;
    float eiv[4], mv[4], lsum[4];
    unsigned long long acc01 = 0ull, acc23 = 0ull;   // f32x2 pairs (a0,a1),(a2,a3)
    #pragma unroll
    for (int ii = 0; ii < 4; ii++) {
        int i = i0 + ii;
        eiv[ii] = g_ei[bh*N_ + i];
        float s = eiv[ii] + g_maxej[bh*N_ + i];
        mv[ii] = (s > 0.f) ? s : NEG_SLOPE * s;
        lsum[ii] = 0.f;
    }

    const float* ht_base = g_ht + (size_t)bh*HD_*N_;
    const float* ej_base = g_ej + bh*N_;
    const int*   adj0 = adj + (size_t)(i0+0)*N_;
    const int*   adj1 = adj + (size_t)(i0+1)*N_;
    const int*   adj2 = adj + (size_t)(i0+2)*N_;
    const int*   adj3 = adj + (size_t)(i0+3)*N_;

    for (int j0 = 0; j0 < N_; j0 += CH) {
        __syncthreads();   // protect hs_t against previous chunk's readers
        // stage h^T chunk: hs_t[d][jj] <- g_ht[bh*HD+d][j0+jj], coalesced f4
        #pragma unroll
        for (int q = tid; q < HD_*(CH/4); q += 256) {
            int d  = q >> 5;          // CH/4 = 32
            int j4 = q & 31;
            *(float4*)&hs_t[d][j4*4] =
                *(const float4*)(ht_base + (size_t)d*N_ + j0 + j4*4);
        }
        __syncthreads();

        #pragma unroll 1
        for (int js = 0; js < CH; js += 32) {
            int j = j0 + js + lane;
            float ejv = ej_base[j];
            int a0 = adj0[j], a1 = adj1[j], a2 = adj2[j], a3 = adj3[j];

            float4 pv;
            {
                float s, lk;
                s = eiv[0] + ejv; lk = (s > 0.f) ? s : NEG_SLOPE*s;
                pv.x = a0 ? __expf(lk - mv[0]) : 0.f;
                s = eiv[1] + ejv; lk = (s > 0.f) ? s : NEG_SLOPE*s;
                pv.y = a1 ? __expf(lk - mv[1]) : 0.f;
                s = eiv[2] + ejv; lk = (s > 0.f) ? s : NEG_SLOPE*s;
                pv.z = a2 ? __expf(lk - mv[2]) : 0.f;
                s = eiv[3] + ejv; lk = (s > 0.f) ? s : NEG_SLOPE*s;
                pv.w = a3 ? __expf(lk - mv[3]) : 0.f;
            }
            lsum[0] += pv.x; lsum[1] += pv.y; lsum[2] += pv.z; lsum[3] += pv.w;
            *(float4*)&ps2[w][lane][0] = pv;     // one STS.128, conflict-free
            __syncwarp();

            #pragma unroll
            for (int k = 0; k < 32; k += 4) {
                float4 hv4 = *(const float4*)&hs_t[lane][js + k];  // 4 j at once
                #pragma unroll
                for (int j2 = 0; j2 < 4; j2++) {
                    // broadcast LDS.128: (p0,p1),(p2,p3) already f32x2-paired
                    ulonglong2 pq = *(const ulonglong2*)&ps2[w][k + j2][0];
                    float hv = (j2 == 0) ? hv4.x : (j2 == 1) ? hv4.y
                             : (j2 == 2) ? hv4.z : hv4.w;
                    unsigned long long hh;
                    asm("mov.b64 %0, {%1, %1};" : "=l"(hh) : "f"(hv));
                    asm("fma.rn.f32x2 %0, %1, %2, %0;"
                        : "+l"(acc01) : "l"(pq.x), "l"(hh));
                    asm("fma.rn.f32x2 %0, %1, %2, %0;"
                        : "+l"(acc23) : "l"(pq.y), "l"(hh));
                }
            }
            __syncwarp();   // before ps2 is overwritten by next group
        }
    }

    float accs[4];
    asm("mov.b64 {%0, %1}, %2;" : "=f"(accs[0]), "=f"(accs[1]) : "l"(acc01));
    asm("mov.b64 {%0, %1}, %2;" : "=f"(accs[2]), "=f"(accs[3]) : "l"(acc23));

    #pragma unroll
    for (int ii = 0; ii < 4; ii++) {
        float l = lsum[ii];
        #pragma unroll
        for (int off = 16; off > 0; off >>= 1)
            l += __shfl_xor_sync(0xffffffffu, l, off);
        out[((size_t)(b*N_ + i0 + ii))*DIN + head*HD_ + lane] =
            accs[ii] * __fdividef(1.f, l);
    }
}

// ---------------------------------------------------------------------------
extern "C" void kernel_launch(void* const* d_in, const int* in_sizes, int n_in,
                              void* d_out, int out_size) {
    const float* x   = (const float*)d_in[0];
    const int*   adj = (const int*)  d_in[1];
    const float* W   = (const float*)d_in[2];
    const float* a   = (const float*)d_in[3];
    float* out = (float*)d_out;

    k_transpose<<<DIN, DIN>>>(W);
    k_gemm<<<(B_*N_)/32, 128>>>(x, a);
    k_maxej<<<N_, 256>>>(adj);
    dim3 grid(BH, N_/32);
    k_attn<<<grid, 256>>>(adj, out);
}

// round 9
// speedup vs baseline: 1.1975x; 1.1975x over previous
#include <cuda_runtime.h>

#define B_ 4
#define N_ 2048
#define DIN 128
#define H_ 4
#define HD_ 32
#define BH (B_*H_)
#define NEG_SLOPE 0.2f
#define CH 128            // j-chunk staged in smem

// Scratch (device globals: no allocation allowed in kernel_launch)
__device__ float g_ht[BH*HD_*N_];      // h TRANSPOSED: [(b*H+h)*HD+d][n]
__device__ float g_Wt4[DIN*DIN];       // W repacked: [k>>2][o][k&3]
__device__ float g_ei[BH*N_];
__device__ float g_ej[BH*N_];
__device__ float g_maxej[BH*N_];       // masked row-max of ej per (b,h,i)
__device__ unsigned g_adjb[(N_/32)*N_];// adjacency bits: [j>>5][i], bit = j&31

// ---------------------------------------------------------------------------
// Kernel 0: repack W -> g_Wt4[(k>>2)*DIN*4 + o*4 + (k&3)]
// ---------------------------------------------------------------------------
__global__ void k_transpose(const float* __restrict__ W) {
    int k = blockIdx.x, o = threadIdx.x;
    g_Wt4[(k >> 2)*(DIN*4) + o*4 + (k & 3)] = W[o*DIN + k];
}

// ---------------------------------------------------------------------------
// Kernel 0b: adjacency bitmask via ballot. warp per i, loop over 32-j words.
// ---------------------------------------------------------------------------
__global__ void __launch_bounds__(256) k_adjbits(const int* __restrict__ adj) {
    int w = threadIdx.x >> 5, lane = threadIdx.x & 31;
    int i = blockIdx.x*8 + w;
    const int* row = adj + (size_t)i*N_;
    #pragma unroll 4
    for (int jw = 0; jw < N_/32; jw++) {
        unsigned word = __ballot_sync(0xffffffffu, row[jw*32 + lane] != 0);
        if (lane == 0) g_adjb[jw*N_ + i] = word;
    }
}

// ---------------------------------------------------------------------------
// Kernel 1: h = x @ W^T (+ fused ei/ej), h stored TRANSPOSED.
// Per 4-k: 1 LDG.128 (w) + 32 broadcast LDS.128 (x) + 128 FFMA.
// ---------------------------------------------------------------------------
__global__ void __launch_bounds__(128) k_gemm(const float* __restrict__ x,
                                              const float* __restrict__ a) {
    __shared__ float xs[32][DIN];
    int row0 = blockIdx.x * 32;
    int tid = threadIdx.x;

    const float4* xsrc = (const float4*)(x + (size_t)row0 * DIN);
    float4* xdst = (float4*)&xs[0][0];
    #pragma unroll
    for (int t = tid; t < 32*DIN/4; t += 128) xdst[t] = xsrc[t];
    __syncthreads();

    int o = tid;
    float acc[32];
    #pragma unroll
    for (int r = 0; r < 32; r++) acc[r] = 0.f;

    #pragma unroll 4
    for (int k4 = 0; k4 < DIN/4; k4++) {
        float4 wv = *(const float4*)&g_Wt4[k4*(DIN*4) + o*4];
        #pragma unroll
        for (int r = 0; r < 32; r++) {
            float4 xv = *(const float4*)&xs[r][k4*4];
            acc[r] += xv.x*wv.x;
            acc[r] += xv.y*wv.y;
            acc[r] += xv.z*wv.z;
            acc[r] += xv.w*wv.w;
        }
    }

    int head = tid >> 5, d = tid & 31;
    int b = row0 / N_;                 // block is inside one batch (N_%32==0)
    int bh = b*H_ + head;

    size_t base = ((size_t)bh*HD_ + d)*N_ + (row0 % N_);
    #pragma unroll
    for (int r4 = 0; r4 < 8; r4++) {
        *(float4*)&g_ht[base + r4*4] =
            make_float4(acc[r4*4+0], acc[r4*4+1], acc[r4*4+2], acc[r4*4+3]);
    }

    float a1 = a[head*2*HD_ + d];
    float a2 = a[head*2*HD_ + HD_ + d];
    #pragma unroll
    for (int r = 0; r < 32; r++) {
        float p1 = acc[r] * a1;
        float p2 = acc[r] * a2;
        #pragma unroll
        for (int off = 16; off > 0; off >>= 1) {
            p1 += __shfl_xor_sync(0xffffffffu, p1, off);
            p2 += __shfl_xor_sync(0xffffffffu, p2, off);
        }
        if (d == 0) {
            int n = (row0 % N_) + r;
            g_ei[bh*N_ + n] = p1;
            g_ej[bh*N_ + n] = p2;
        }
    }
}

// ---------------------------------------------------------------------------
// Kernel 2: masked row-max of ej (leaky monotone => softmax row max is
// leaky(ei + max_{adj} ej), computed without touching h). Uses bitmask.
// ---------------------------------------------------------------------------
__global__ void __launch_bounds__(256) k_maxej() {
    int i = blockIdx.x;
    int tid = threadIdx.x;
    const float NEG_INF = __int_as_float(0xff800000);

    float m[BH];
    #pragma unroll
    for (int q = 0; q < BH; q++) m[q] = NEG_INF;

    for (int j = tid; j < N_; j += 256) {
        unsigned word = g_adjb[(j >> 5)*N_ + i];
        if ((word >> (j & 31)) & 1u) {
            #pragma unroll
            for (int q = 0; q < BH; q++) m[q] = fmaxf(m[q], g_ej[q*N_ + j]);
        }
    }

    __shared__ float red[8][BH];
    #pragma unroll
    for (int q = 0; q < BH; q++) {
        float v = m[q];
        #pragma unroll
        for (int off = 16; off > 0; off >>= 1)
            v = fmaxf(v, __shfl_xor_sync(0xffffffffu, v, off));
        m[q] = v;
    }
    if ((tid & 31) == 0) {
        #pragma unroll
        for (int q = 0; q < BH; q++) red[tid >> 5][q] = m[q];
    }
    __syncthreads();
    if (tid < BH) {
        float v = red[0][tid];
        #pragma unroll
        for (int w2 = 1; w2 < 8; w2++) v = fmaxf(v, red[w2][tid]);
        g_maxej[tid*N_ + i] = v;
    }
}

// ---------------------------------------------------------------------------
// Kernel 3: fused masked softmax + aggregation.
// grid = (16 bh, 32 tiles of 64 i). 8 warps; warp owns 8 i-rows (lane = d).
//   - 4 packed f32x2 accumulator chains (spacing 4 >= FFMA lat) per warp
//   - p pre-paired in pp[warp][chain][j] (u64): STS.64 conflict-free,
//     broadcast ulonglong2 loads feed 2 j per chain
//   - hs_t[d][j] (+16B pad) transposed h chunk: LDS.128 = 4 j per load
//   - adjacency via 2 broadcast LDG.128 of bitmask words per 32-j
// ---------------------------------------------------------------------------
__global__ void __launch_bounds__(256) k_attn(float* __restrict__ out) {
    __shared__ float hs_t[HD_][CH+4];                        // ~16.9 KB
    __shared__ __align__(16) unsigned long long pp[8][4][32];// 8 KB

    int bh = blockIdx.x;
    int b = bh >> 2, head = bh & 3;
    int tid = threadIdx.x, w = tid >> 5, lane = tid & 31;

    int i0 = blockIdx.y*64 + w*8;
    float eiv[8], mv[8], lsum[8];
    unsigned long long acc[4] = {0ull, 0ull, 0ull, 0ull};  // (i0+2c, i0+2c+1)
    #pragma unroll
    for (int ii = 0; ii < 8; ii++) {
        int i = i0 + ii;
        eiv[ii] = g_ei[bh*N_ + i];
        float s = eiv[ii] + g_maxej[bh*N_ + i];
        mv[ii] = fmaxf(s, NEG_SLOPE * s);
        lsum[ii] = 0.f;
    }

    const float* ht_base = g_ht + (size_t)bh*HD_*N_;
    const float* ej_base = g_ej + bh*N_;

    for (int j0 = 0; j0 < N_; j0 += CH) {
        __syncthreads();   // protect hs_t against previous chunk's readers
        #pragma unroll
        for (int q = tid; q < HD_*(CH/4); q += 256) {
            int d  = q >> 5;          // CH/4 = 32
            int j4 = q & 31;
            *(float4*)&hs_t[d][j4*4] =
                *(const float4*)(ht_base + (size_t)d*N_ + j0 + j4*4);
        }
        __syncthreads();

        #pragma unroll 1
        for (int js = 0; js < CH; js += 32) {
            // ---- score phase: lane = j ----
            int j = j0 + js + lane;
            float ejv = __ldg(ej_base + j);
            int jw = (j0 + js) >> 5;
            uint4 wa = *(const uint4*)(g_adjb + jw*N_ + i0);     // i0..i0+3
            uint4 wb = *(const uint4*)(g_adjb + jw*N_ + i0 + 4); // i0+4..i0+7

            float pv[8];
            unsigned wbits[8] = {wa.x, wa.y, wa.z, wa.w, wb.x, wb.y, wb.z, wb.w};
            #pragma unroll
            for (int ii = 0; ii < 8; ii++) {
                float s = eiv[ii] + ejv;
                float lk = fmaxf(s, NEG_SLOPE * s);
                float e = __expf(lk - mv[ii]);
                float p = ((wbits[ii] >> lane) & 1u) ? e : 0.f;
                lsum[ii] += p;
                pv[ii] = p;
            }
            #pragma unroll
            for (int c = 0; c < 4; c++) {
                unsigned long long u;
                asm("mov.b64 %0, {%1, %2};" : "=l"(u)
                    : "f"(pv[2*c]), "f"(pv[2*c+1]));
                pp[w][c][lane] = u;
            }
            __syncwarp();

            // ---- FMA phase: lane = d ----
            #pragma unroll
            for (int k = 0; k < 32; k += 4) {
                float4 hv4 = *(const float4*)&hs_t[lane][js + k];
                unsigned long long h0, h1, h2, h3;
                asm("mov.b64 %0, {%1, %1};" : "=l"(h0) : "f"(hv4.x));
                asm("mov.b64 %0, {%1, %1};" : "=l"(h1) : "f"(hv4.y));
                asm("mov.b64 %0, {%1, %1};" : "=l"(h2) : "f"(hv4.z));
                asm("mov.b64 %0, {%1, %1};" : "=l"(h3) : "f"(hv4.w));
                {   // j = k, k+1
                    ulonglong2 q0 = *(const ulonglong2*)&pp[w][0][k];
                    ulonglong2 q1 = *(const ulonglong2*)&pp[w][1][k];
                    ulonglong2 q2 = *(const ulonglong2*)&pp[w][2][k];
                    ulonglong2 q3 = *(const ulonglong2*)&pp[w][3][k];
                    asm("fma.rn.f32x2 %0, %1, %2, %0;" : "+l"(acc[0]) : "l"(q0.x), "l"(h0));
                    asm("fma.rn.f32x2 %0, %1, %2, %0;" : "+l"(acc[1]) : "l"(q1.x), "l"(h0));
                    asm("fma.rn.f32x2 %0, %1, %2, %0;" : "+l"(acc[2]) : "l"(q2.x), "l"(h0));
                    asm("fma.rn.f32x2 %0, %1, %2, %0;" : "+l"(acc[3]) : "l"(q3.x), "l"(h0));
                    asm("fma.rn.f32x2 %0, %1, %2, %0;" : "+l"(acc[0]) : "l"(q0.y), "l"(h1));
                    asm("fma.rn.f32x2 %0, %1, %2, %0;" : "+l"(acc[1]) : "l"(q1.y), "l"(h1));
                    asm("fma.rn.f32x2 %0, %1, %2, %0;" : "+l"(acc[2]) : "l"(q2.y), "l"(h1));
                    asm("fma.rn.f32x2 %0, %1, %2, %0;" : "+l"(acc[3]) : "l"(q3.y), "l"(h1));
                }
                {   // j = k+2, k+3
                    ulonglong2 q0 = *(const ulonglong2*)&pp[w][0][k+2];
                    ulonglong2 q1 = *(const ulonglong2*)&pp[w][1][k+2];
                    ulonglong2 q2 = *(const ulonglong2*)&pp[w][2][k+2];
                    ulonglong2 q3 = *(const ulonglong2*)&pp[w][3][k+2];
                    asm("fma.rn.f32x2 %0, %1, %2, %0;" : "+l"(acc[0]) : "l"(q0.x), "l"(h2));
                    asm("fma.rn.f32x2 %0, %1, %2, %0;" : "+l"(acc[1]) : "l"(q1.x), "l"(h2));
                    asm("fma.rn.f32x2 %0, %1, %2, %0;" : "+l"(acc[2]) : "l"(q2.x), "l"(h2));
                    asm("fma.rn.f32x2 %0, %1, %2, %0;" : "+l"(acc[3]) : "l"(q3.x), "l"(h2));
                    asm("fma.rn.f32x2 %0, %1, %2, %0;" : "+l"(acc[0]) : "l"(q0.y), "l"(h3));
                    asm("fma.rn.f32x2 %0, %1, %2, %0;" : "+l"(acc[1]) : "l"(q1.y), "l"(h3));
                    asm("fma.rn.f32x2 %0, %1, %2, %0;" : "+l"(acc[2]) : "l"(q2.y), "l"(h3));
                    asm("fma.rn.f32x2 %0, %1, %2, %0;" : "+l"(acc[3]) : "l"(q3.y), "l"(h3));
                }
            }
            __syncwarp();   // before pp is overwritten by next group
        }
    }

    float accs[8];
    #pragma unroll
    for (int c = 0; c < 4; c++)
        asm("mov.b64 {%0, %1}, %2;"
            : "=f"(accs[2*c]), "=f"(accs[2*c+1]) : "l"(acc[c]));

    #pragma unroll
    for (int ii = 0; ii < 8; ii++) {
        float l = lsum[ii];
        #pragma unroll
        for (int off = 16; off > 0; off >>= 1)
            l += __shfl_xor_sync(0xffffffffu, l, off);
        out[((size_t)(b*N_ + i0 + ii))*DIN + head*HD_ + lane] =
            accs[ii] * __fdividef(1.f, l);
    }
}

// ---------------------------------------------------------------------------
extern "C" void kernel_launch(void* const* d_in, const int* in_sizes, int n_in,
                              void* d_out, int out_size) {
    const float* x   = (const float*)d_in[0];
    const int*   adj = (const int*)  d_in[1];
    const float* W   = (const float*)d_in[2];
    const float* a   = (const float*)d_in[3];
    float* out = (float*)d_out;

    k_transpose<<<DIN, DIN>>>(W);
    k_adjbits<<<N_/8, 256>>>(adj);
    k_gemm<<<(B_*N_)/32, 128>>>(x, a);
    k_maxej<<<N_, 256>>>();
    dim3 grid(BH, N_/64);
    k_attn<<<grid, 256>>>(out);
}

// round 13
// speedup vs baseline: 1.6152x; 1.3488x over previous
#include <cuda_runtime.h>

#define B_ 4
#define N_ 2048
#define DIN 128
#define H_ 4
#define HD_ 32
#define BH (B_*H_)
#define NEG_SLOPE 0.2f
#define L2E 1.4426950408889634f

typedef unsigned int u32;

// Scratch (device globals: no allocation allowed in kernel_launch)
__device__ float g_Wt4[DIN*DIN];          // W repacked: [k>>2][o][k&3]
__device__ float g_ei[BH*N_];
__device__ float g_ej[BH*N_];
__device__ float g_maxbh[BH];             // UNMASKED max_j ej per (b,h)
__device__ unsigned g_adjb[(N_/32)*N_];   // adjacency bits: [j>>5][i], bit = j&31
__device__ u32 g_hb_hi[BH*HD_*N_/2];      // h^T bf16 hi pairs: [(bh*HD+d)][n/2]
__device__ u32 g_hb_lo[BH*HD_*N_/2];      // h^T bf16 lo pairs (h - hi)

// ---------------------------------------------------------------------------
// helpers
// ---------------------------------------------------------------------------
__device__ __forceinline__ u32 bf16x2_rn(float hi, float lo) {
    u32 r;
    asm("cvt.rn.bf16x2.f32 %0, %1, %2;" : "=r"(r) : "f"(hi), "f"(lo));
    return r;   // upper 16 = hi arg, lower 16 = lo arg
}
__device__ __forceinline__ float pcalc(float ei, float ej, float mvl, u32 on) {
    float s = ei + ej;
    float lk = fmaxf(s, NEG_SLOPE * s);
    float t = fmaf(lk, L2E, mvl);          // mvl = -mv*log2e (pre-negated)
    float e;
    asm("ex2.approx.f32 %0, %1;" : "=f"(e) : "f"(t));
    return (on & 1u) ? e : 0.f;
}
__device__ __forceinline__ void mma16816(float* c, u32 a0, u32 a1, u32 a2, u32 a3,
                                         u32 b0, u32 b1) {
    asm("mma.sync.aligned.m16n8k16.row.col.f32.bf16.bf16.f32 "
        "{%0,%1,%2,%3}, {%4,%5,%6,%7}, {%8,%9}, {%0,%1,%2,%3};"
        : "+f"(c[0]), "+f"(c[1]), "+f"(c[2]), "+f"(c[3])
        : "r"(a0), "r"(a1), "r"(a2), "r"(a3), "r"(b0), "r"(b1));
}

// ---------------------------------------------------------------------------
// Kernel 0: repack W -> g_Wt4[(k>>2)*DIN*4 + o*4 + (k&3)]
// ---------------------------------------------------------------------------
__global__ void k_transpose(const float* __restrict__ W) {
    int k = blockIdx.x, o = threadIdx.x;
    g_Wt4[(k >> 2)*(DIN*4) + o*4 + (k & 3)] = W[o*DIN + k];
}

// ---------------------------------------------------------------------------
// Kernel 0b: adjacency bitmask via ballot
// ---------------------------------------------------------------------------
__global__ void __launch_bounds__(256) k_adjbits(const int* __restrict__ adj) {
    int w = threadIdx.x >> 5, lane = threadIdx.x & 31;
    int i = blockIdx.x*8 + w;
    const int* row = adj + (size_t)i*N_;
    #pragma unroll 4
    for (int jw = 0; jw < N_/32; jw++) {
        unsigned word = __ballot_sync(0xffffffffu, row[jw*32 + lane] != 0);
        if (lane == 0) g_adjb[jw*N_ + i] = word;
    }
}

// ---------------------------------------------------------------------------
// Kernel 1: h = x @ W^T (+ fused ei/ej). h stored TRANSPOSED as bf16 hi/lo
// pairs (error-compensated split feeding the HMMA B fragments directly).
// ---------------------------------------------------------------------------
__global__ void __launch_bounds__(128) k_gemm(const float* __restrict__ x,
                                              const float* __restrict__ a) {
    __shared__ float xs[32][DIN];
    int row0 = blockIdx.x * 32;
    int tid = threadIdx.x;

    const float4* xsrc = (const float4*)(x + (size_t)row0 * DIN);
    float4* xdst = (float4*)&xs[0][0];
    #pragma unroll
    for (int t = tid; t < 32*DIN/4; t += 128) xdst[t] = xsrc[t];
    __syncthreads();

    int o = tid;
    float acc[32];
    #pragma unroll
    for (int r = 0; r < 32; r++) acc[r] = 0.f;

    #pragma unroll 4
    for (int k4 = 0; k4 < DIN/4; k4++) {
        float4 wv = *(const float4*)&g_Wt4[k4*(DIN*4) + o*4];
        #pragma unroll
        for (int r = 0; r < 32; r++) {
            float4 xv = *(const float4*)&xs[r][k4*4];
            acc[r] += xv.x*wv.x;
            acc[r] += xv.y*wv.y;
            acc[r] += xv.z*wv.z;
            acc[r] += xv.w*wv.w;
        }
    }

    int head = tid >> 5, d = tid & 31;
    int b = row0 / N_;
    int bh = b*H_ + head;

    // bf16 hi/lo split of h, stored transposed [(bh*HD+d)][n] as u32 pairs,
    // even n in the LOW half (matches mma B-fragment register layout)
    size_t nb = ((size_t)bh*HD_ + d)*N_ + (row0 % N_);
    u32 hw[16], lw[16];
    #pragma unroll
    for (int t = 0; t < 16; t++) {
        float p0 = acc[2*t], p1 = acc[2*t+1];
        u32 h = bf16x2_rn(p1, p0);
        float h0 = __uint_as_float(h << 16);
        float h1 = __uint_as_float(h & 0xffff0000u);
        hw[t] = h;
        lw[t] = bf16x2_rn(p1 - h1, p0 - h0);
    }
    #pragma unroll
    for (int t4 = 0; t4 < 4; t4++) {
        *(uint4*)(g_hb_hi + nb/2 + t4*4) =
            make_uint4(hw[t4*4], hw[t4*4+1], hw[t4*4+2], hw[t4*4+3]);
        *(uint4*)(g_hb_lo + nb/2 + t4*4) =
            make_uint4(lw[t4*4], lw[t4*4+1], lw[t4*4+2], lw[t4*4+3]);
    }

    float a1 = a[head*2*HD_ + d];
    float a2 = a[head*2*HD_ + HD_ + d];
    #pragma unroll
    for (int r = 0; r < 32; r++) {
        float p1 = acc[r] * a1;
        float p2 = acc[r] * a2;
        #pragma unroll
        for (int off = 16; off > 0; off >>= 1) {
            p1 += __shfl_xor_sync(0xffffffffu, p1, off);
            p2 += __shfl_xor_sync(0xffffffffu, p2, off);
        }
        if (d == 0) {
            int n = (row0 % N_) + r;
            g_ei[bh*N_ + n] = p1;
            g_ej[bh*N_ + n] = p2;
        }
    }
}

// ---------------------------------------------------------------------------
// Kernel 2: UNMASKED max_j ej per (b,h). Monotone leaky => per-row shift
// leaky(ei + M_bh) upper-bounds the true masked row max; softmax ratios are
// shift-invariant, so this is exact (exponents <= 0, no overflow).
// ---------------------------------------------------------------------------
__global__ void __launch_bounds__(256) k_maxbh() {
    int bh = blockIdx.x;
    int tid = threadIdx.x, lane = tid & 31;
    float m = __int_as_float(0xff800000);
    const float* p = g_ej + bh*N_;
    #pragma unroll 4
    for (int j = tid; j < N_; j += 256) m = fmaxf(m, p[j]);
    #pragma unroll
    for (int off = 16; off > 0; off >>= 1)
        m = fmaxf(m, __shfl_xor_sync(0xffffffffu, m, off));
    __shared__ float red[8];
    if (lane == 0) red[tid >> 5] = m;
    __syncthreads();
    if (tid == 0) {
        float v = red[0];
        #pragma unroll
        for (int q = 1; q < 8; q++) v = fmaxf(v, red[q]);
        g_maxbh[bh] = v;
    }
}

// ---------------------------------------------------------------------------
// Kernel 3: fused masked softmax + HMMA aggregation. NO shared memory, NO
// __syncthreads. Block = 4 warps; warp owns one 16-row M-tile of one (b,h).
// Scores are computed straight into m16n8k16 A-fragment registers (bf16
// hi/lo split); B fragments are direct u32 loads from g_hb (layout matches
// the fragment exactly). 3 mma terms: Ph*Hh + Pl*Hh + Ph*Hl. Row sums stay
// in registers (quad shfl) and scale the C fragments at the end.
// ---------------------------------------------------------------------------
__global__ void __launch_bounds__(128) k_attn(float* __restrict__ out) {
    int bh = blockIdx.x;
    int b = bh >> 2, head = bh & 3;
    int tid = threadIdx.x, w = tid >> 5, lane = tid & 31;
    int gid = lane >> 2, tig = lane & 3;

    int r0 = blockIdx.y*64 + w*16 + gid;      // absolute i rows of this thread
    int r1 = r0 + 8;

    float ei0 = g_ei[bh*N_ + r0];
    float ei1 = g_ei[bh*N_ + r1];
    float M = g_maxbh[bh];
    float s0 = ei0 + M, s1 = ei1 + M;
    float mvl0 = -fmaxf(s0, NEG_SLOPE*s0) * L2E;   // pre-negated log2-domain
    float mvl1 = -fmaxf(s1, NEG_SLOPE*s1) * L2E;

    float sum0 = 0.f, sum1 = 0.f;
    float acc[4][4];
    #pragma unroll
    for (int nt = 0; nt < 4; nt++)
        #pragma unroll
        for (int q = 0; q < 4; q++) acc[nt][q] = 0.f;

    const float* ejp = g_ej + bh*N_;
    const u32* hbH = g_hb_hi + (size_t)bh*HD_*(N_/2) + (size_t)gid*(N_/2) + tig;
    const u32* hbL = g_hb_lo + (size_t)bh*HD_*(N_/2) + (size_t)gid*(N_/2) + tig;

    unsigned w0 = 0, w1 = 0;
    #pragma unroll 2
    for (int c = 0; c < N_/16; c++) {
        int j0 = c*16;
        if ((c & 1) == 0) {
            w0 = g_adjb[(j0 >> 5)*N_ + r0];
            w1 = g_adjb[(j0 >> 5)*N_ + r1];
        }
        int sh = (c & 1) << 4;

        float2 ejA = *(const float2*)(ejp + j0 + 2*tig);
        float2 ejB = *(const float2*)(ejp + j0 + 8 + 2*tig);
        unsigned bA0 = w0 >> (sh + 2*tig);
        unsigned bB0 = w0 >> (sh + 8 + 2*tig);
        unsigned bA1 = w1 >> (sh + 2*tig);
        unsigned bB1 = w1 >> (sh + 8 + 2*tig);

        float p00 = pcalc(ei0, ejA.x, mvl0, bA0);
        float p01 = pcalc(ei0, ejA.y, mvl0, bA0 >> 1);
        float p02 = pcalc(ei0, ejB.x, mvl0, bB0);
        float p03 = pcalc(ei0, ejB.y, mvl0, bB0 >> 1);
        float p10 = pcalc(ei1, ejA.x, mvl1, bA1);
        float p11 = pcalc(ei1, ejA.y, mvl1, bA1 >> 1);
        float p12 = pcalc(ei1, ejB.x, mvl1, bB1);
        float p13 = pcalc(ei1, ejB.y, mvl1, bB1 >> 1);

        sum0 += (p00 + p01) + (p02 + p03);
        sum1 += (p10 + p11) + (p12 + p13);

        // A fragments: a0=(r0, jA), a1=(r1, jA), a2=(r0, jB), a3=(r1, jB)
        u32 a0h = bf16x2_rn(p01, p00);
        u32 a1h = bf16x2_rn(p11, p10);
        u32 a2h = bf16x2_rn(p03, p02);
        u32 a3h = bf16x2_rn(p13, p12);
        u32 a0l, a1l, a2l, a3l;
        {
            float q0, q1;
            q0 = __uint_as_float(a0h << 16); q1 = __uint_as_float(a0h & 0xffff0000u);
            a0l = bf16x2_rn(p01 - q1, p00 - q0);
            q0 = __uint_as_float(a1h << 16); q1 = __uint_as_float(a1h & 0xffff0000u);
            a1l = bf16x2_rn(p11 - q1, p10 - q0);
            q0 = __uint_as_float(a2h << 16); q1 = __uint_as_float(a2h & 0xffff0000u);
            a2l = bf16x2_rn(p03 - q1, p02 - q0);
            q0 = __uint_as_float(a3h << 16); q1 = __uint_as_float(a3h & 0xffff0000u);
            a3l = bf16x2_rn(p13 - q1, p12 - q0);
        }

        int jof = j0 >> 1;
        #pragma unroll
        for (int nt = 0; nt < 4; nt++) {
            const u32* bp = hbH + (size_t)nt*8*(N_/2) + jof;
            const u32* bq = hbL + (size_t)nt*8*(N_/2) + jof;
            u32 b0h = bp[0], b1h = bp[4];
            u32 b0l = bq[0], b1l = bq[4];
            mma16816(acc[nt], a0h, a1h, a2h, a3h, b0h, b1h);
            mma16816(acc[nt], a0l, a1l, a2l, a3l, b0h, b1h);
            mma16816(acc[nt], a0h, a1h, a2h, a3h, b0l, b1l);
        }
    }

    // full row sums: reduce across the 4 lanes of the quad (same gid)
    sum0 += __shfl_xor_sync(0xffffffffu, sum0, 1);
    sum0 += __shfl_xor_sync(0xffffffffu, sum0, 2);
    sum1 += __shfl_xor_sync(0xffffffffu, sum1, 1);
    sum1 += __shfl_xor_sync(0xffffffffu, sum1, 2);
    float inv0 = __fdividef(1.f, sum0);
    float inv1 = __fdividef(1.f, sum1);

    // C fragment: (r0, 2tig),(r0, 2tig+1),(r1, 2tig),(r1, 2tig+1) per n-tile
    float* d0 = out + ((size_t)(b*N_ + r0))*DIN + head*HD_ + 2*tig;
    float* d1 = out + ((size_t)(b*N_ + r1))*DIN + head*HD_ + 2*tig;
    #pragma unroll
    for (int nt = 0; nt < 4; nt++) {
        float2 v0 = make_float2(acc[nt][0]*inv0, acc[nt][1]*inv0);
        float2 v1 = make_float2(acc[nt][2]*inv1, acc[nt][3]*inv1);
        *(float2*)(d0 + nt*8) = v0;
        *(float2*)(d1 + nt*8) = v1;
    }
}

// ---------------------------------------------------------------------------
extern "C" void kernel_launch(void* const* d_in, const int* in_sizes, int n_in,
                              void* d_out, int out_size) {
    const float* x   = (const float*)d_in[0];
    const int*   adj = (const int*)  d_in[1];
    const float* W   = (const float*)d_in[2];
    const float* a   = (const float*)d_in[3];
    float* out = (float*)d_out;

    k_transpose<<<DIN, DIN>>>(W);
    k_adjbits<<<N_/8, 256>>>(adj);
    k_gemm<<<(B_*N_)/32, 128>>>(x, a);
    k_maxbh<<<BH, 256>>>();
    dim3 grid(BH, N_/64);
    k_attn<<<grid, 128>>>(out);
}